// round 4
// baseline (speedup 1.0000x reference)
#include <cuda_runtime.h>
#include <math.h>

// ---------------- device scratch (static: allocations are forbidden) -------
// Conv A operand, fragment-major for mma.m16n8k8 tf32:
// [par(8)][c(64)][mt(6)][lane(32)][reg(4)]  (tf32 bit patterns)
__device__ unsigned g_Afrag[8 * 64 * 6 * 32 * 4];
// Combine A operand, fragment-major: [k2(12)][mt(2)][lane(32)][reg(4)]
__device__ unsigned g_A2frag[12 * 2 * 32 * 4];
__device__ float g_bias1[32];
__device__ float g_bias2[32];

// ---------------- helpers ----------------------------------------------------
__device__ __forceinline__ unsigned f2tf(float f) {
    unsigned r;
    asm("cvt.rna.tf32.f32 %0, %1;" : "=r"(r) : "f"(f));
    return r;
}

__device__ __forceinline__ void mma_tf32(float* d, const unsigned* a,
                                         unsigned b0, unsigned b1) {
    asm volatile(
        "mma.sync.aligned.m16n8k8.row.col.f32.tf32.tf32.f32 "
        "{%0,%1,%2,%3}, {%4,%5,%6,%7}, {%8,%9}, {%0,%1,%2,%3};"
        : "+f"(d[0]), "+f"(d[1]), "+f"(d[2]), "+f"(d[3])
        : "r"(a[0]), "r"(a[1]), "r"(a[2]), "r"(a[3]), "r"(b0), "r"(b1));
}

__device__ __forceinline__ void cp_async16(unsigned dstS, const void* src) {
    asm volatile("cp.async.cg.shared.global [%0], [%1], 16;" :: "r"(dstS), "l"(src));
}

// per-axis trilinear->original-grid collapse weights
__device__ __forceinline__ double hval(int q, int k, int e, double a) {
    if (q == 0) {
        if (k == 0) return e ? a : (1.0 - a);
        return e ? 1.0 : 0.0;
    } else {
        if (k == 2) return e ? (1.0 - a) : a;
        return e ? 0.0 : 1.0;
    }
}

// ---------------- merged setup kernel ----------------------------------------
// grid (64 c, 8 par), block 192 = 6 mt x 32 lanes. Block (0,0) also folds
// BN params into combine fragments and biases.
__global__ void setup_all(const float* __restrict__ W,
                          const float* __restrict__ g1, const float* __restrict__ v1,
                          const float* __restrict__ b_def,
                          const float* __restrict__ b1, const float* __restrict__ m1,
                          const float* __restrict__ wcm, const float* __restrict__ bcm,
                          const float* __restrict__ g2, const float* __restrict__ b2,
                          const float* __restrict__ m2, const float* __restrict__ v2) {
    __shared__ float ws[32 * 27];
    int c = blockIdx.x, par = blockIdx.y;
    int tid = threadIdx.x;
    for (int idx = tid; idx < 32 * 27; idx += 192) {
        int co = idx / 27, kk = idx - co * 27;
        ws[idx] = W[co * 1728 + c * 27 + kk];
    }
    __syncthreads();

    int mt = tid >> 5, lane = tid & 31;
    int g = lane >> 2, t = lane & 3;
    int qz = (par >> 2) & 1, qy = (par >> 1) & 1, qx = par & 1;

#pragma unroll
    for (int r = 0; r < 4; r++) {
        int m = mt * 16 + g + 8 * (r & 1);
        int tap = t + 4 * (r >> 1);
        int br = m >> 5, co = m & 31;
        double a = (br == 0) ? 0.0 : (br == 1 ? 0.4 : 0.7);
        int ez = (tap >> 2) & 1, ey = (tap >> 1) & 1, ex = tap & 1;

        double hz[3], hy[3], hx[3];
#pragma unroll
        for (int k = 0; k < 3; k++) {
            hz[k] = hval(qz, k, ez, a);
            hy[k] = hval(qy, k, ey, a);
            hx[k] = hval(qx, k, ex, a);
        }
        float sum = 0.f;
#pragma unroll
        for (int kz = 0; kz < 3; kz++)
#pragma unroll
            for (int ky = 0; ky < 3; ky++)
#pragma unroll
                for (int kx = 0; kx < 3; kx++)
                    sum += ws[co * 27 + kz * 9 + ky * 3 + kx] *
                           (float)(hz[kz] * hy[ky] * hx[kx]);
        float s1 = g1[co] * rsqrtf(v1[co] + 1e-5f);
        g_Afrag[(((par * 64 + c) * 6 + mt) * 32 + lane) * 4 + r] = f2tf(sum * s1);
    }

    if (blockIdx.x == 0 && blockIdx.y == 0) {
        if (tid < 32) {
            float s1 = g1[tid] * rsqrtf(v1[tid] + 1e-5f);
            g_bias1[tid] = b_def[tid] * s1 + b1[tid] - m1[tid] * s1;
            float s2 = g2[tid] * rsqrtf(v2[tid] + 1e-5f);
            g_bias2[tid] = bcm[tid] * s2 + b2[tid] - m2[tid] * s2;
        }
        for (int idx = tid; idx < 12 * 2 * 32 * 4; idx += 192) {
            int r = idx & 3, ln = (idx >> 2) & 31, mt2 = (idx >> 7) & 1, k2 = idx >> 8;
            int gg = ln >> 2, tt = ln & 3;
            int m = mt2 * 16 + gg + 8 * (r & 1);
            int cp = k2 * 8 + tt + 4 * (r >> 1);
            float s2 = g2[m] * rsqrtf(v2[m] + 1e-5f);
            g_A2frag[idx] = f2tf(wcm[m * 96 + cp] * s2);
        }
    }
}

// ---------------- main fused kernel ------------------------------------------
// block 256 thr = 8 warps; tile = 8(x) x 8(y) x 4(z) orig coords = 256 voxels,
// one parity class. Conv GEMM D[96][256] then combine GEMM D2[32][256].
#define XT_FLOATS 25920          // x tile [64c][5z][9y][9x]; reused as R[96][264]
#define SA_FLOATS 18432          // 3 x (8c * 6mt * 32 * 4) triple-buffered A
#define SA2_FLOATS 3072
#define SMEM_BYTES ((XT_FLOATS + SA_FLOATS + SA2_FLOATS + 64) * 4)
#define RSTRIDE 264

__global__ void __launch_bounds__(256)
conv_main(const float* __restrict__ x, float* __restrict__ out) {
    extern __shared__ float sm[];
    float* xt = sm;                                // also R after conv
    float* sA = sm + XT_FLOATS;
    float* sA2 = sm + XT_FLOATS + SA_FLOATS;
    float* b1s = sA2 + SA2_FLOATS;
    float* b2s = b1s + 32;

    const int tid = threadIdx.x;
    const int w = tid >> 5, lane = tid & 31;
    const int g = lane >> 2, t = lane & 3;

    const int par = blockIdx.z >> 3;
    const int pzt = blockIdx.z & 7;
    const int qz = (par >> 2) & 1, qy = (par >> 1) & 1, qx = par & 1;
    const int Px0 = blockIdx.x * 8, Py0 = blockIdx.y * 8, Pz0 = pzt * 4;
    const int ox = Px0 - 1 + qx, oy = Py0 - 1 + qy, oz = Pz0 - 1 + qz;

    // ---- prefetch conv-A chunks 0 and 1 (3-stage pipeline) ----
    const unsigned* gA = g_Afrag + par * 64 * 768;   // 768 unsigned per c
    unsigned sA_base;
    {
        unsigned long long p = (unsigned long long)__cvta_generic_to_shared(sA);
        sA_base = (unsigned)p;
    }
#pragma unroll
    for (int i = 0; i < 6; i++)
        cp_async16(sA_base + (i * 256 + tid) * 16, gA + (i * 256 + tid) * 4);
    asm volatile("cp.async.commit_group;");
#pragma unroll
    for (int i = 0; i < 6; i++)
        cp_async16(sA_base + 6144 * 4 + (i * 256 + tid) * 16,
                   gA + 6144 + (i * 256 + tid) * 4);
    asm volatile("cp.async.commit_group;");

    // ---- load x tile (hoisted coords, tf32-rounded, zero at borders) ----
    {
        int p0 = tid;
        int z0 = p0 / 81, r0 = p0 - z0 * 81, y0 = r0 / 9, x0 = r0 - y0 * 9;
        int gz0 = oz + z0, gy0 = oy + y0, gx0 = ox + x0;
        bool ok0 = ((unsigned)gz0 < 32u) && ((unsigned)gy0 < 32u) && ((unsigned)gx0 < 32u);
        int off0 = (gz0 * 32 + gy0) * 32 + gx0;

        int p1 = tid + 256;
        bool has1 = p1 < 405;
        int z1 = p1 / 81, r1 = p1 - z1 * 81, y1 = r1 / 9, x1 = r1 - y1 * 9;
        int gz1 = oz + z1, gy1 = oy + y1, gx1 = ox + x1;
        bool ok1 = has1 && ((unsigned)gz1 < 32u) && ((unsigned)gy1 < 32u) &&
                   ((unsigned)gx1 < 32u);
        int off1 = (gz1 * 32 + gy1) * 32 + gx1;

        unsigned* xtu_w = (unsigned*)xt;
#pragma unroll 4
        for (int c = 0; c < 64; c++) {
            float v = ok0 ? __ldg(x + c * 32768 + off0) : 0.f;
            xtu_w[c * 405 + p0] = f2tf(v);
            if (has1) {
                float u = ok1 ? __ldg(x + c * 32768 + off1) : 0.f;
                xtu_w[c * 405 + p1] = f2tf(u);
            }
        }
    }
    // combine A fragments + biases
    for (int idx = tid; idx < SA2_FLOATS; idx += 256)
        ((unsigned*)sA2)[idx] = g_A2frag[idx];
    if (tid < 32) { b1s[tid] = g_bias1[tid]; b2s[tid] = g_bias2[tid]; }

    // ---- per-lane B gather offsets ----
    int boff[4];
#pragma unroll
    for (int nt = 0; nt < 4; nt++) {
        int vv = 4 * w + nt;
        boff[nt] = (vv >> 3) * 81 + (vv & 7) * 9 + g;
    }
    const int toff = (t >> 1) * 9 + (t & 1);
    const unsigned* xtu = (const unsigned*)xt;

    float d[6][4][4];
#pragma unroll
    for (int i = 0; i < 6; i++)
#pragma unroll
        for (int j = 0; j < 4; j++)
#pragma unroll
            for (int r = 0; r < 4; r++) d[i][j][r] = 0.f;

    // ---- conv GEMM: K = 512 (64 c x 8 taps), 8 chunks of 8 c ----
#pragma unroll 1
    for (int kc = 0; kc < 8; kc++) {
        if (kc == 7) { asm volatile("cp.async.wait_group 0;"); }
        else         { asm volatile("cp.async.wait_group 1;"); }
        __syncthreads();
        if (kc < 6) {
            unsigned dstS = sA_base + ((kc + 2) % 3) * 6144 * 4;
            const unsigned* src = gA + (kc + 2) * 6144;
#pragma unroll
            for (int i = 0; i < 6; i++)
                cp_async16(dstS + (i * 256 + tid) * 16, src + (i * 256 + tid) * 4);
            asm volatile("cp.async.commit_group;");
        }
        const unsigned* Ab = (const unsigned*)sA + (kc % 3) * 6144;

        unsigned bb[2][2][4];
        {
            const int cbase = (kc * 8) * 405 + toff;
#pragma unroll
            for (int nt = 0; nt < 4; nt++) {
                bb[0][0][nt] = xtu[cbase + boff[nt]];
                bb[0][1][nt] = xtu[cbase + boff[nt] + 81];
            }
        }
#pragma unroll
        for (int ci = 0; ci < 8; ci++) {
            const int cur = ci & 1, nxt = cur ^ 1;
            if (ci < 7) {
                const int cb2 = (kc * 8 + ci + 1) * 405 + toff;
#pragma unroll
                for (int nt = 0; nt < 4; nt++) {
                    bb[nxt][0][nt] = xtu[cb2 + boff[nt]];
                    bb[nxt][1][nt] = xtu[cb2 + boff[nt] + 81];
                }
            }
#pragma unroll
            for (int mt = 0; mt < 6; mt++) {
                unsigned a[4];
                *(uint4*)a = *(const uint4*)(Ab + ((ci * 6 + mt) * 32 + lane) * 4);
#pragma unroll
                for (int nt = 0; nt < 4; nt++)
                    mma_tf32(d[mt][nt], a, bb[cur][0][nt], bb[cur][1][nt]);
            }
        }
    }

    // ---- relu + bias1, stage R[96][264] into xt region (tf32-rounded) ----
    __syncthreads();   // all B gathers from xt are done
#pragma unroll
    for (int mt = 0; mt < 6; mt++)
#pragma unroll
        for (int nt = 0; nt < 4; nt++)
#pragma unroll
            for (int r = 0; r < 4; r++) {
                int m = mt * 16 + g + 8 * (r >> 1);
                int vox = w * 32 + nt * 8 + 2 * t + (r & 1);
                float v = fmaxf(d[mt][nt][r] + b1s[m & 31], 0.f);
                ((unsigned*)xt)[m * RSTRIDE + vox] = f2tf(v);
            }
    __syncthreads();

    // ---- combine GEMM: D2[32][256] = A2[32][96] * R ----
    float e[2][4][4];
#pragma unroll
    for (int i = 0; i < 2; i++)
#pragma unroll
        for (int j = 0; j < 4; j++)
#pragma unroll
            for (int r = 0; r < 4; r++) e[i][j][r] = 0.f;

    const unsigned* Ru = (const unsigned*)xt;
#pragma unroll
    for (int k2 = 0; k2 < 12; k2++) {
        unsigned bb0[4], bb1[4];
#pragma unroll
        for (int nt = 0; nt < 4; nt++) {
            int col = w * 32 + nt * 8 + g;
            bb0[nt] = Ru[(k2 * 8 + t) * RSTRIDE + col];
            bb1[nt] = Ru[(k2 * 8 + t + 4) * RSTRIDE + col];
        }
#pragma unroll
        for (int mt = 0; mt < 2; mt++) {
            unsigned a[4];
            *(uint4*)a = *(const uint4*)((const unsigned*)sA2 +
                                         ((k2 * 2 + mt) * 32 + lane) * 4);
#pragma unroll
            for (int nt = 0; nt < 4; nt++)
                mma_tf32(e[mt][nt], a, bb0[nt], bb1[nt]);
        }
    }

    // ---- bias2 + relu + store ----
#pragma unroll
    for (int mt = 0; mt < 2; mt++)
#pragma unroll
        for (int nt = 0; nt < 4; nt++)
#pragma unroll
            for (int r = 0; r < 4; r++) {
                int o = mt * 16 + g + 8 * (r >> 1);
                int vox = w * 32 + nt * 8 + 2 * t + (r & 1);
                int vx = vox & 7, vy = (vox >> 3) & 7, vz = vox >> 6;
                int gx = 2 * (Px0 + vx) + qx;
                int gy = 2 * (Py0 + vy) + qy;
                int gz = 2 * (Pz0 + vz) + qz;
                out[o * 262144 + gz * 4096 + gy * 64 + gx] =
                    fmaxf(e[mt][nt][r] + b2s[o], 0.f);
            }
}

// ---------------- launch -----------------------------------------------------
extern "C" void kernel_launch(void* const* d_in, const int* in_sizes, int n_in,
                              void* d_out, int out_size) {
    const float* x      = (const float*)d_in[0];
    const float* w_def  = (const float*)d_in[1];
    const float* b_def  = (const float*)d_in[2];
    const float* bn1_g  = (const float*)d_in[3];
    const float* bn1_b  = (const float*)d_in[4];
    const float* bn1_m  = (const float*)d_in[5];
    const float* bn1_v  = (const float*)d_in[6];
    const float* w_comb = (const float*)d_in[7];
    const float* b_comb = (const float*)d_in[8];
    const float* bn2_g  = (const float*)d_in[9];
    const float* bn2_b  = (const float*)d_in[10];
    const float* bn2_m  = (const float*)d_in[11];
    const float* bn2_v  = (const float*)d_in[12];

    setup_all<<<dim3(64, 8), 192>>>(w_def, bn1_g, bn1_v, b_def, bn1_b, bn1_m,
                                    w_comb, b_comb, bn2_g, bn2_b, bn2_m, bn2_v);

    cudaFuncSetAttribute(conv_main, cudaFuncAttributeMaxDynamicSharedMemorySize,
                         SMEM_BYTES);
    conv_main<<<dim3(4, 4, 64), 256, SMEM_BYTES>>>(x, (float*)d_out);
}

// round 5
// speedup vs baseline: 1.6714x; 1.6714x over previous
#include <cuda_runtime.h>
#include <cuda_fp16.h>
#include <math.h>

// ---------------- device scratch (static: allocations are forbidden) -------
// Conv A operand, fp16x2 fragment-major for mma.m16n8k16:
// [par(8)][kc(8)][cpi(4)][mt(6)][lane(32)][r(4)]  (each u32 = fp16x2)
__device__ unsigned g_A16[8 * 8 * 3072];
// Combine A operand: [k2(6)][mt(2)][lane(32)][r(4)] fp16x2
__device__ unsigned g_A2[1536];
__device__ float g_bias1[32];
__device__ float g_bias2[32];

// ---------------- helpers ----------------------------------------------------
__device__ __forceinline__ void mma_f16(float* d, const unsigned* a,
                                        unsigned b0, unsigned b1) {
    asm volatile(
        "mma.sync.aligned.m16n8k16.row.col.f32.f16.f16.f32 "
        "{%0,%1,%2,%3}, {%4,%5,%6,%7}, {%8,%9}, {%0,%1,%2,%3};"
        : "+f"(d[0]), "+f"(d[1]), "+f"(d[2]), "+f"(d[3])
        : "r"(a[0]), "r"(a[1]), "r"(a[2]), "r"(a[3]), "r"(b0), "r"(b1));
}

__device__ __forceinline__ void cp_async16(unsigned dstS, const void* src) {
    asm volatile("cp.async.cg.shared.global [%0], [%1], 16;" :: "r"(dstS), "l"(src));
}

// per-axis trilinear->original-grid collapse weights
__device__ __forceinline__ double hval(int q, int k, int e, double a) {
    if (q == 0) {
        if (k == 0) return e ? a : (1.0 - a);
        return e ? 1.0 : 0.0;
    } else {
        if (k == 2) return e ? (1.0 - a) : a;
        return e ? 0.0 : 1.0;
    }
}

// ---------------- merged setup kernel ----------------------------------------
// grid (64 c, 8 par), block 192 = 6 mt x 32 lanes.
__global__ void setup_all(const float* __restrict__ W,
                          const float* __restrict__ g1, const float* __restrict__ v1,
                          const float* __restrict__ b_def,
                          const float* __restrict__ b1, const float* __restrict__ m1,
                          const float* __restrict__ wcm, const float* __restrict__ bcm,
                          const float* __restrict__ g2, const float* __restrict__ b2,
                          const float* __restrict__ m2, const float* __restrict__ v2) {
    __shared__ float ws[32 * 27];
    int c = blockIdx.x, par = blockIdx.y;
    int tid = threadIdx.x;
    for (int idx = tid; idx < 32 * 27; idx += 192) {
        int co = idx / 27, kk = idx - co * 27;
        ws[idx] = W[co * 1728 + c * 27 + kk];
    }
    __syncthreads();

    int mt = tid >> 5, lane = tid & 31;
    int g = lane >> 2, t4 = lane & 3;
    int qz = (par >> 2) & 1, qy = (par >> 1) & 1, qx = par & 1;

#pragma unroll
    for (int rowbit = 0; rowbit < 2; rowbit++) {
        int m = mt * 16 + g + 8 * rowbit;
        int br = m >> 5, co = m & 31;
        double a = (br == 0) ? 0.0 : (br == 1 ? 0.4 : 0.7);
        float s1 = g1[co] * rsqrtf(v1[co] + 1e-5f);
        __half hh[2];
#pragma unroll
        for (int h = 0; h < 2; h++) {
            int tap = 2 * t4 + h;
            int ez = (tap >> 2) & 1, ey = (tap >> 1) & 1, ex = tap & 1;
            double hz[3], hy[3], hx[3];
#pragma unroll
            for (int k = 0; k < 3; k++) {
                hz[k] = hval(qz, k, ez, a);
                hy[k] = hval(qy, k, ey, a);
                hx[k] = hval(qx, k, ex, a);
            }
            float sum = 0.f;
#pragma unroll
            for (int kz = 0; kz < 3; kz++)
#pragma unroll
                for (int ky = 0; ky < 3; ky++)
#pragma unroll
                    for (int kx = 0; kx < 3; kx++)
                        sum += ws[co * 27 + kz * 9 + ky * 3 + kx] *
                               (float)(hz[kz] * hy[ky] * hx[kx]);
            hh[h] = __float2half(sum * s1);
        }
        int r = 2 * (c & 1) + rowbit;
        int idx = ((((par * 8 + (c >> 3)) * 4 + ((c >> 1) & 3)) * 6 + mt) * 32 + lane) * 4 + r;
        __half2 hv = __halves2half2(hh[0], hh[1]);
        g_A16[idx] = *(unsigned*)&hv;
    }

    if (blockIdx.x == 0 && blockIdx.y == 0) {
        if (tid < 32) {
            float s1 = g1[tid] * rsqrtf(v1[tid] + 1e-5f);
            g_bias1[tid] = b_def[tid] * s1 + b1[tid] - m1[tid] * s1;
            float s2 = g2[tid] * rsqrtf(v2[tid] + 1e-5f);
            g_bias2[tid] = bcm[tid] * s2 + b2[tid] - m2[tid] * s2;
        }
        for (int idx = tid; idx < 1536; idx += 192) {
            int r = idx & 3, ln = (idx >> 2) & 31, mt2 = (idx >> 7) & 1, k2 = idx >> 8;
            int gg = ln >> 2, tt = ln & 3;
            int m = mt2 * 16 + gg + 8 * (r & 1);
            float s2 = g2[m] * rsqrtf(v2[m] + 1e-5f);
            int ch0 = k2 * 16 + 8 * (r >> 1) + 2 * tt;
            __half2 hv = __halves2half2(__float2half(wcm[m * 96 + ch0] * s2),
                                        __float2half(wcm[m * 96 + ch0 + 1] * s2));
            g_A2[idx] = *(unsigned*)&hv;
        }
    }
}

// ---------------- main fused kernel ------------------------------------------
// block 256 thr = 8 warps; tile = 8(x) x 8(y) x 4(z) orig coords = 256 voxels,
// one parity class. x tile held 32 channels at a time (2 phases) as overlapping
// fp16x2 pairs; conv GEMM fp16 D[96][256]; combine GEMM fp16 D2[32][256].
#define XT_U32 12960            // 32c * 405 positions (fp16x2 pairs)
#define SA_U32 6144             // 2 x 3072 double-buffered A chunks
#define SA2_U32 1536
#define SMEM_BYTES ((XT_U32 + SA_U32 + SA2_U32 + 64) * 4)

__global__ void __launch_bounds__(256, 2)
conv_main(const float* __restrict__ x, float* __restrict__ out) {
    extern __shared__ unsigned smu[];
    unsigned* xt = smu;                         // also R_t after conv
    unsigned* sA = smu + XT_U32;
    unsigned* sA2 = sA + SA_U32;
    float* b1s = (float*)(sA2 + SA2_U32);
    float* b2s = b1s + 32;

    const int tid = threadIdx.x;
    const int w = tid >> 5, lane = tid & 31;
    const int g = lane >> 2, t4 = lane & 3;

    const int par = blockIdx.z >> 3;
    const int pzt = blockIdx.z & 7;
    const int qz = (par >> 2) & 1, qy = (par >> 1) & 1, qx = par & 1;
    const int Px0 = blockIdx.x * 8, Py0 = blockIdx.y * 8, Pz0 = pzt * 4;
    const int ox = Px0 - 1 + qx, oy = Py0 - 1 + qy, oz = Pz0 - 1 + qz;

    // ---- prefetch conv-A chunk 0 ----
    const unsigned* gA = g_A16 + par * 24576;
    unsigned sA_addr;
    {
        unsigned long long p = (unsigned long long)__cvta_generic_to_shared(sA);
        sA_addr = (unsigned)p;
    }
    for (int i = tid; i < 768; i += 256)
        cp_async16(sA_addr + i * 16, gA + i * 4);
    asm volatile("cp.async.commit_group;");

    // ---- x-tile half loader: 32 channels as overlapping fp16 pairs ----
    auto load_half = [&](int phase) {
        const float* xb = x + phase * 32 * 32768;
        __half* hp = (__half*)xt;
        for (int idx = tid; idx < XT_U32; idx += 256) {
            int c = idx / 405;
            int pos = idx - c * 405;
            int z = pos / 81;
            int rr = pos - z * 81;
            int y = rr / 9;
            int xx = rr - y * 9;
            int gz = oz + z, gy = oy + y, gx = ox + xx;
            float v = 0.f;
            if ((unsigned)gz < 32u && (unsigned)gy < 32u && (unsigned)gx < 32u)
                v = __ldg(xb + (c * 32 + gz) * 1024 + gy * 32 + gx);
            __half h = __float2half(v);
            hp[2 * idx] = h;                 // low half of pair idx
            if (pos) hp[2 * idx - 1] = h;    // high half of pair idx-1
        }
    };

    load_half(0);
    for (int i = tid; i < SA2_U32; i += 256) sA2[i] = g_A2[i];
    if (tid < 32) { b1s[tid] = g_bias1[tid]; b2s[tid] = g_bias2[tid]; }

    // ---- per-lane B gather offsets ----
    int boff[4];
#pragma unroll
    for (int nt = 0; nt < 4; nt++) {
        int vox = w * 32 + nt * 8 + g;
        boff[nt] = (vox >> 6) * 81 + ((vox >> 3) & 7) * 9 + (vox & 7);
    }
    const int tapoff = (t4 >> 1) * 81 + (t4 & 1) * 9;

    float d[6][4][4];
#pragma unroll
    for (int i = 0; i < 6; i++)
#pragma unroll
        for (int j = 0; j < 4; j++)
#pragma unroll
            for (int r = 0; r < 4; r++) d[i][j][r] = 0.f;

    // ---- conv GEMM: K = 512 (64 c x 8 taps), 8 chunks of 8 channels ----
#pragma unroll 1
    for (int kc = 0; kc < 8; kc++) {
        asm volatile("cp.async.wait_group 0;");
        __syncthreads();
        if (kc < 7) {
            unsigned dst = sA_addr + ((kc + 1) & 1) * 3072 * 4;
            const unsigned* src = gA + (kc + 1) * 3072;
            for (int i = tid; i < 768; i += 256)
                cp_async16(dst + i * 16, src + i * 4);
            asm volatile("cp.async.commit_group;");
        }
        if (kc == 4) {          // phase boundary: reload x tile with channels 32..63
            load_half(1);
            __syncthreads();
        }
        const unsigned* Ab = sA + (kc & 1) * 3072;
        const int cbase = (kc & 3) * 8;          // local channel base in this half

        unsigned bb[2][2][4];
        {
            const int cw = cbase * 405 + tapoff;
#pragma unroll
            for (int nt = 0; nt < 4; nt++) {
                bb[0][0][nt] = xt[cw + boff[nt]];
                bb[0][1][nt] = xt[cw + boff[nt] + 405];
            }
        }
#pragma unroll
        for (int cpi = 0; cpi < 4; cpi++) {
            const int cur = cpi & 1, nxt = cur ^ 1;
            if (cpi < 3) {
                const int cw = (cbase + 2 * (cpi + 1)) * 405 + tapoff;
#pragma unroll
                for (int nt = 0; nt < 4; nt++) {
                    bb[nxt][0][nt] = xt[cw + boff[nt]];
                    bb[nxt][1][nt] = xt[cw + boff[nt] + 405];
                }
            }
#pragma unroll
            for (int mt = 0; mt < 6; mt++) {
                unsigned a[4];
                *(uint4*)a = *(const uint4*)(Ab + (cpi * 6 + mt) * 128 + lane * 4);
#pragma unroll
                for (int nt = 0; nt < 4; nt++)
                    mma_f16(d[mt][nt], a, bb[cur][0][nt], bb[cur][1][nt]);
            }
        }
    }

    // ---- relu + bias1, stage R_t[vox][96ch] fp16 (stride 100) over xt ----
    __syncthreads();   // all B gathers from xt are done
    {
        __half* Rt = (__half*)xt;
#pragma unroll
        for (int mt = 0; mt < 6; mt++)
#pragma unroll
            for (int nt = 0; nt < 4; nt++)
#pragma unroll
                for (int r = 0; r < 4; r++) {
                    int m = mt * 16 + g + 8 * (r >> 1);
                    int vox = w * 32 + nt * 8 + 2 * t4 + (r & 1);
                    float v = fmaxf(d[mt][nt][r] + b1s[m & 31], 0.f);
                    Rt[vox * 100 + m] = __float2half(v);
                }
    }
    __syncthreads();

    // ---- combine GEMM: D2[32][256] = A2[32][96] * R ----
    float e[2][4][4];
#pragma unroll
    for (int i = 0; i < 2; i++)
#pragma unroll
        for (int j = 0; j < 4; j++)
#pragma unroll
            for (int r = 0; r < 4; r++) e[i][j][r] = 0.f;

#pragma unroll
    for (int k2 = 0; k2 < 6; k2++) {
        unsigned bb0[4], bb1[4];
#pragma unroll
        for (int nt = 0; nt < 4; nt++) {
            int col = w * 32 + nt * 8 + g;
            int base = col * 50 + k2 * 8 + t4;   // u32 index into R_t
            bb0[nt] = xt[base];
            bb1[nt] = xt[base + 4];
        }
#pragma unroll
        for (int mt = 0; mt < 2; mt++) {
            unsigned a[4];
            *(uint4*)a = *(const uint4*)(sA2 + (k2 * 2 + mt) * 128 + lane * 4);
#pragma unroll
            for (int nt = 0; nt < 4; nt++)
                mma_f16(e[mt][nt], a, bb0[nt], bb1[nt]);
        }
    }

    // ---- bias2 + relu + store ----
#pragma unroll
    for (int mt = 0; mt < 2; mt++)
#pragma unroll
        for (int nt = 0; nt < 4; nt++)
#pragma unroll
            for (int r = 0; r < 4; r++) {
                int o = mt * 16 + g + 8 * (r >> 1);
                int vox = w * 32 + nt * 8 + 2 * t4 + (r & 1);
                int vx = vox & 7, vy = (vox >> 3) & 7, vz = vox >> 6;
                int gx = 2 * (Px0 + vx) + qx;
                int gy = 2 * (Py0 + vy) + qy;
                int gz = 2 * (Pz0 + vz) + qz;
                out[o * 262144 + gz * 4096 + gy * 64 + gx] =
                    fmaxf(e[mt][nt][r] + b2s[o], 0.f);
            }
}

// ---------------- launch -----------------------------------------------------
extern "C" void kernel_launch(void* const* d_in, const int* in_sizes, int n_in,
                              void* d_out, int out_size) {
    const float* x      = (const float*)d_in[0];
    const float* w_def  = (const float*)d_in[1];
    const float* b_def  = (const float*)d_in[2];
    const float* bn1_g  = (const float*)d_in[3];
    const float* bn1_b  = (const float*)d_in[4];
    const float* bn1_m  = (const float*)d_in[5];
    const float* bn1_v  = (const float*)d_in[6];
    const float* w_comb = (const float*)d_in[7];
    const float* b_comb = (const float*)d_in[8];
    const float* bn2_g  = (const float*)d_in[9];
    const float* bn2_b  = (const float*)d_in[10];
    const float* bn2_m  = (const float*)d_in[11];
    const float* bn2_v  = (const float*)d_in[12];

    setup_all<<<dim3(64, 8), 192>>>(w_def, bn1_g, bn1_v, b_def, bn1_b, bn1_m,
                                    w_comb, b_comb, bn2_g, bn2_b, bn2_m, bn2_v);

    cudaFuncSetAttribute(conv_main, cudaFuncAttributeMaxDynamicSharedMemorySize,
                         SMEM_BYTES);
    conv_main<<<dim3(4, 4, 64), 256, SMEM_BYTES>>>(x, (float*)d_out);
}

// round 6
// speedup vs baseline: 2.0189x; 1.2079x over previous
#include <cuda_runtime.h>
#include <cuda_fp16.h>
#include <math.h>

// ---------------- device scratch (static: allocations are forbidden) -------
// Conv A operand, fp16x2 fragment-major for mma.m16n8k16:
// [par(8)][kc(8)][cpi(4)][mt(6)][lane(32)][r(4)]  (each u32 = fp16x2)
__device__ unsigned g_A16[8 * 8 * 3072];
// Combine A operand: [k2(6)][mt(2)][lane(32)][r(4)] fp16x2
__device__ unsigned g_A2[1536];
__device__ float g_bias1[32];
__device__ float g_bias2[32];

// ---------------- helpers ----------------------------------------------------
__device__ __forceinline__ void mma_f16(float* d, const unsigned* a,
                                        unsigned b0, unsigned b1) {
    asm volatile(
        "mma.sync.aligned.m16n8k16.row.col.f32.f16.f16.f32 "
        "{%0,%1,%2,%3}, {%4,%5,%6,%7}, {%8,%9}, {%0,%1,%2,%3};"
        : "+f"(d[0]), "+f"(d[1]), "+f"(d[2]), "+f"(d[3])
        : "r"(a[0]), "r"(a[1]), "r"(a[2]), "r"(a[3]), "r"(b0), "r"(b1));
}

__device__ __forceinline__ void cp_async16(unsigned dstS, const void* src) {
    asm volatile("cp.async.cg.shared.global [%0], [%1], 16;" :: "r"(dstS), "l"(src));
}

// per-axis trilinear->original-grid collapse weights (fp32: values are exact
// small rationals; error ~1e-7 is invisible under fp16 quantization)
__device__ __forceinline__ float hvalf(int q, int k, int e, float a) {
    if (q == 0) {
        if (k == 0) return e ? a : (1.0f - a);
        return e ? 1.0f : 0.0f;
    } else {
        if (k == 2) return e ? (1.0f - a) : a;
        return e ? 0.0f : 1.0f;
    }
}

// ---------------- merged setup kernel ----------------------------------------
// grid (64 c, 8 par), block 192 = 6 mt x 32 lanes.
__global__ void setup_all(const float* __restrict__ W,
                          const float* __restrict__ g1, const float* __restrict__ v1,
                          const float* __restrict__ b_def,
                          const float* __restrict__ b1, const float* __restrict__ m1,
                          const float* __restrict__ wcm, const float* __restrict__ bcm,
                          const float* __restrict__ g2, const float* __restrict__ b2,
                          const float* __restrict__ m2, const float* __restrict__ v2) {
    __shared__ float ws[32 * 27];
    int c = blockIdx.x, par = blockIdx.y;
    int tid = threadIdx.x;
    for (int idx = tid; idx < 32 * 27; idx += 192) {
        int co = idx / 27, kk = idx - co * 27;
        ws[idx] = W[co * 1728 + c * 27 + kk];
    }
    __syncthreads();

    int mt = tid >> 5, lane = tid & 31;
    int g = lane >> 2, t4 = lane & 3;
    int qz = (par >> 2) & 1, qy = (par >> 1) & 1, qx = par & 1;

#pragma unroll
    for (int rowbit = 0; rowbit < 2; rowbit++) {
        int m = mt * 16 + g + 8 * rowbit;
        int br = m >> 5, co = m & 31;
        float a = (br == 0) ? 0.0f : (br == 1 ? 0.4f : 0.7f);
        float s1 = g1[co] * rsqrtf(v1[co] + 1e-5f);
        __half hh[2];
#pragma unroll
        for (int h = 0; h < 2; h++) {
            int tap = 2 * t4 + h;
            int ez = (tap >> 2) & 1, ey = (tap >> 1) & 1, ex = tap & 1;
            float hz[3], hy[3], hx[3];
#pragma unroll
            for (int k = 0; k < 3; k++) {
                hz[k] = hvalf(qz, k, ez, a);
                hy[k] = hvalf(qy, k, ey, a);
                hx[k] = hvalf(qx, k, ex, a);
            }
            float sum = 0.f;
#pragma unroll
            for (int kz = 0; kz < 3; kz++)
#pragma unroll
                for (int ky = 0; ky < 3; ky++)
#pragma unroll
                    for (int kx = 0; kx < 3; kx++)
                        sum += ws[co * 27 + kz * 9 + ky * 3 + kx] *
                               (hz[kz] * hy[ky] * hx[kx]);
            hh[h] = __float2half(sum * s1);
        }
        int r = 2 * (c & 1) + rowbit;
        int idx = ((((par * 8 + (c >> 3)) * 4 + ((c >> 1) & 3)) * 6 + mt) * 32 + lane) * 4 + r;
        __half2 hv = __halves2half2(hh[0], hh[1]);
        g_A16[idx] = *(unsigned*)&hv;
    }

    if (blockIdx.x == 0 && blockIdx.y == 0) {
        if (tid < 32) {
            float s1 = g1[tid] * rsqrtf(v1[tid] + 1e-5f);
            g_bias1[tid] = b_def[tid] * s1 + b1[tid] - m1[tid] * s1;
            float s2 = g2[tid] * rsqrtf(v2[tid] + 1e-5f);
            g_bias2[tid] = bcm[tid] * s2 + b2[tid] - m2[tid] * s2;
        }
        for (int idx = tid; idx < 1536; idx += 192) {
            int r = idx & 3, ln = (idx >> 2) & 31, mt2 = (idx >> 7) & 1, k2 = idx >> 8;
            int gg = ln >> 2, tt = ln & 3;
            int m = mt2 * 16 + gg + 8 * (r & 1);
            float s2 = g2[m] * rsqrtf(v2[m] + 1e-5f);
            int ch0 = k2 * 16 + 8 * (r >> 1) + 2 * tt;
            __half2 hv = __halves2half2(__float2half(wcm[m * 96 + ch0] * s2),
                                        __float2half(wcm[m * 96 + ch0 + 1] * s2));
            g_A2[idx] = *(unsigned*)&hv;
        }
    }
}

// ---------------- main fused kernel ------------------------------------------
// block 256 thr = 8 warps; tile = 8(x) x 8(y) x 4(z) orig coords = 256 voxels,
// one parity class. x tile held 32 channels at a time (2 phases) as overlapping
// fp16x2 pairs; conv GEMM fp16 D[96][256]; combine GEMM fp16 D2[32][256].
#define XT_U32 12960            // 32c * 405 positions (fp16x2 pairs)
#define SA_U32 6144             // 2 x 3072 double-buffered A chunks
#define SA2_U32 1536
#define SMEM_BYTES ((XT_U32 + SA_U32 + SA2_U32 + 64) * 4)

__global__ void __launch_bounds__(256, 2)
conv_main(const float* __restrict__ x, float* __restrict__ out) {
    extern __shared__ unsigned smu[];
    unsigned* xt = smu;                         // also R_t after conv
    unsigned* sA = smu + XT_U32;
    unsigned* sA2 = sA + SA_U32;
    float* b1s = (float*)(sA2 + SA2_U32);
    float* b2s = b1s + 32;

    const int tid = threadIdx.x;
    const int w = tid >> 5, lane = tid & 31;
    const int g = lane >> 2, t4 = lane & 3;

    const int par = blockIdx.z >> 3;
    const int pzt = blockIdx.z & 7;
    const int qz = (par >> 2) & 1, qy = (par >> 1) & 1, qx = par & 1;
    const int Px0 = blockIdx.x * 8, Py0 = blockIdx.y * 8, Pz0 = pzt * 4;
    const int ox = Px0 - 1 + qx, oy = Py0 - 1 + qy, oz = Pz0 - 1 + qz;

    // ---- prefetch conv-A chunk 0 ----
    const unsigned* gA = g_A16 + par * 24576;
    unsigned sA_addr;
    {
        unsigned long long p = (unsigned long long)__cvta_generic_to_shared(sA);
        sA_addr = (unsigned)p;
    }
    for (int i = tid; i < 768; i += 256)
        cp_async16(sA_addr + i * 16, gA + i * 4);
    asm volatile("cp.async.commit_group;");

    // ---- hoisted loader coords: 2 fixed tile positions per thread ----
    const int p0 = tid;                       // 0..255 (<405 always)
    int z0 = p0 / 81, r0 = p0 - z0 * 81, y0 = r0 / 9, x0 = r0 - y0 * 9;
    int gz0 = oz + z0, gy0 = oy + y0, gx0 = ox + x0;
    const bool ok0 = ((unsigned)gz0 < 32u) && ((unsigned)gy0 < 32u) &&
                     ((unsigned)gx0 < 32u);
    const int off0 = (gz0 * 32 + gy0) * 32 + gx0;

    const int p1 = tid + 256;
    const bool has1 = p1 < 405;
    int z1 = p1 / 81, r1 = p1 - z1 * 81, y1 = r1 / 9, x1 = r1 - y1 * 9;
    int gz1 = oz + z1, gy1 = oy + y1, gx1 = ox + x1;
    const bool ok1 = has1 && ((unsigned)gz1 < 32u) && ((unsigned)gy1 < 32u) &&
                     ((unsigned)gx1 < 32u);
    const int off1 = (gz1 * 32 + gy1) * 32 + gx1;

    // x tile as overlapping fp16 pairs: pair idx holds halves (pos, pos+1)
    auto load_half = [&](int phase) {
        const float* xb = x + phase * 32 * 32768;
        __half* hp = (__half*)xt;
#pragma unroll 8
        for (int c = 0; c < 32; c++) {
            float v0 = ok0 ? __ldg(xb + c * 32768 + off0) : 0.f;
            __half h0 = __float2half(v0);
            int i0 = c * 405 + p0;
            hp[2 * i0] = h0;
            if (p0) hp[2 * i0 - 1] = h0;
            if (has1) {
                float v1v = ok1 ? __ldg(xb + c * 32768 + off1) : 0.f;
                __half h1 = __float2half(v1v);
                int i1 = c * 405 + p1;
                hp[2 * i1] = h1;
                hp[2 * i1 - 1] = h1;
            }
        }
    };

    load_half(0);
    for (int i = tid; i < SA2_U32; i += 256) sA2[i] = g_A2[i];
    if (tid < 32) { b1s[tid] = g_bias1[tid]; b2s[tid] = g_bias2[tid]; }

    // ---- per-lane B gather offsets ----
    int boff[4];
#pragma unroll
    for (int nt = 0; nt < 4; nt++) {
        int vox = w * 32 + nt * 8 + g;
        boff[nt] = (vox >> 6) * 81 + ((vox >> 3) & 7) * 9 + (vox & 7);
    }
    const int tapoff = (t4 >> 1) * 81 + (t4 & 1) * 9;

    float d[6][4][4];
#pragma unroll
    for (int i = 0; i < 6; i++)
#pragma unroll
        for (int j = 0; j < 4; j++)
#pragma unroll
            for (int r = 0; r < 4; r++) d[i][j][r] = 0.f;

    // ---- conv GEMM: K = 512 (64 c x 8 taps), 8 chunks of 8 channels ----
#pragma unroll 1
    for (int kc = 0; kc < 8; kc++) {
        asm volatile("cp.async.wait_group 0;");
        __syncthreads();
        if (kc < 7) {
            unsigned dst = sA_addr + ((kc + 1) & 1) * 3072 * 4;
            const unsigned* src = gA + (kc + 1) * 3072;
            for (int i = tid; i < 768; i += 256)
                cp_async16(dst + i * 16, src + i * 4);
            asm volatile("cp.async.commit_group;");
        }
        if (kc == 4) {          // phase boundary: reload x tile with channels 32..63
            load_half(1);
            __syncthreads();
        }
        const unsigned* Ab = sA + (kc & 1) * 3072;
        const int cbase = (kc & 3) * 8;          // local channel base in this half

        unsigned bb[2][2][4];
        {
            const int cw = cbase * 405 + tapoff;
#pragma unroll
            for (int nt = 0; nt < 4; nt++) {
                bb[0][0][nt] = xt[cw + boff[nt]];
                bb[0][1][nt] = xt[cw + boff[nt] + 405];
            }
        }
#pragma unroll
        for (int cpi = 0; cpi < 4; cpi++) {
            const int cur = cpi & 1, nxt = cur ^ 1;
            if (cpi < 3) {
                const int cw = (cbase + 2 * (cpi + 1)) * 405 + tapoff;
#pragma unroll
                for (int nt = 0; nt < 4; nt++) {
                    bb[nxt][0][nt] = xt[cw + boff[nt]];
                    bb[nxt][1][nt] = xt[cw + boff[nt] + 405];
                }
            }
#pragma unroll
            for (int mt = 0; mt < 6; mt++) {
                unsigned a[4];
                *(uint4*)a = *(const uint4*)(Ab + (cpi * 6 + mt) * 128 + lane * 4);
#pragma unroll
                for (int nt = 0; nt < 4; nt++)
                    mma_f16(d[mt][nt], a, bb[cur][0][nt], bb[cur][1][nt]);
            }
        }
    }

    // ---- relu + bias1, stage R_t[vox][96ch] fp16 (stride 100) over xt ----
    __syncthreads();   // all B gathers from xt are done
    {
        __half* Rt = (__half*)xt;
#pragma unroll
        for (int mt = 0; mt < 6; mt++)
#pragma unroll
            for (int nt = 0; nt < 4; nt++)
#pragma unroll
                for (int r = 0; r < 4; r++) {
                    int m = mt * 16 + g + 8 * (r >> 1);
                    int vox = w * 32 + nt * 8 + 2 * t4 + (r & 1);
                    float v = fmaxf(d[mt][nt][r] + b1s[m & 31], 0.f);
                    Rt[vox * 100 + m] = __float2half(v);
                }
    }
    __syncthreads();

    // ---- combine GEMM: D2[32][256] = A2[32][96] * R ----
    float e[2][4][4];
#pragma unroll
    for (int i = 0; i < 2; i++)
#pragma unroll
        for (int j = 0; j < 4; j++)
#pragma unroll
            for (int r = 0; r < 4; r++) e[i][j][r] = 0.f;

#pragma unroll
    for (int k2 = 0; k2 < 6; k2++) {
        unsigned bb0[4], bb1[4];
#pragma unroll
        for (int nt = 0; nt < 4; nt++) {
            int col = w * 32 + nt * 8 + g;
            int base = col * 50 + k2 * 8 + t4;   // u32 index into R_t
            bb0[nt] = xt[base];
            bb1[nt] = xt[base + 4];
        }
#pragma unroll
        for (int mt = 0; mt < 2; mt++) {
            unsigned a[4];
            *(uint4*)a = *(const uint4*)(sA2 + (k2 * 2 + mt) * 128 + lane * 4);
#pragma unroll
            for (int nt = 0; nt < 4; nt++)
                mma_f16(e[mt][nt], a, bb0[nt], bb1[nt]);
        }
    }

    // ---- bias2 + relu + store ----
#pragma unroll
    for (int mt = 0; mt < 2; mt++)
#pragma unroll
        for (int nt = 0; nt < 4; nt++)
#pragma unroll
            for (int r = 0; r < 4; r++) {
                int o = mt * 16 + g + 8 * (r >> 1);
                int vox = w * 32 + nt * 8 + 2 * t4 + (r & 1);
                int vx = vox & 7, vy = (vox >> 3) & 7, vz = vox >> 6;
                int gx = 2 * (Px0 + vx) + qx;
                int gy = 2 * (Py0 + vy) + qy;
                int gz = 2 * (Pz0 + vz) + qz;
                out[o * 262144 + gz * 4096 + gy * 64 + gx] =
                    fmaxf(e[mt][nt][r] + b2s[o], 0.f);
            }
}

// ---------------- launch -----------------------------------------------------
extern "C" void kernel_launch(void* const* d_in, const int* in_sizes, int n_in,
                              void* d_out, int out_size) {
    const float* x      = (const float*)d_in[0];
    const float* w_def  = (const float*)d_in[1];
    const float* b_def  = (const float*)d_in[2];
    const float* bn1_g  = (const float*)d_in[3];
    const float* bn1_b  = (const float*)d_in[4];
    const float* bn1_m  = (const float*)d_in[5];
    const float* bn1_v  = (const float*)d_in[6];
    const float* w_comb = (const float*)d_in[7];
    const float* b_comb = (const float*)d_in[8];
    const float* bn2_g  = (const float*)d_in[9];
    const float* bn2_b  = (const float*)d_in[10];
    const float* bn2_m  = (const float*)d_in[11];
    const float* bn2_v  = (const float*)d_in[12];

    setup_all<<<dim3(64, 8), 192>>>(w_def, bn1_g, bn1_v, b_def, bn1_b, bn1_m,
                                    w_comb, b_comb, bn2_g, bn2_b, bn2_m, bn2_v);

    cudaFuncSetAttribute(conv_main, cudaFuncAttributeMaxDynamicSharedMemorySize,
                         SMEM_BYTES);
    conv_main<<<dim3(4, 4, 64), 256, SMEM_BYTES>>>(x, (float*)d_out);
}

// round 7
// speedup vs baseline: 2.0335x; 1.0072x over previous
#include <cuda_runtime.h>
#include <cuda_fp16.h>
#include <math.h>

// ---------------- device scratch (static: allocations are forbidden) -------
// Conv A operand, fp16x2 fragment-major for mma.m16n8k16:
// [par(8)][kc(8)][cpi(4)][mt(6)][lane(32)][r(4)]  (each u32 = fp16x2)
__device__ unsigned g_A16[8 * 8 * 3072];
// Combine A operand: [k2(6)][mt(2)][lane(32)][r(4)] fp16x2
__device__ unsigned g_A2[1536];
__device__ float g_bias1[32];
__device__ float g_bias2[32];

// ---------------- helpers ----------------------------------------------------
__device__ __forceinline__ void mma_f16(float* d, const unsigned* a,
                                        unsigned b0, unsigned b1) {
    asm volatile(
        "mma.sync.aligned.m16n8k16.row.col.f32.f16.f16.f32 "
        "{%0,%1,%2,%3}, {%4,%5,%6,%7}, {%8,%9}, {%0,%1,%2,%3};"
        : "+f"(d[0]), "+f"(d[1]), "+f"(d[2]), "+f"(d[3])
        : "r"(a[0]), "r"(a[1]), "r"(a[2]), "r"(a[3]), "r"(b0), "r"(b1));
}

__device__ __forceinline__ void mbar_init(unsigned mbar, unsigned count) {
    asm volatile("mbarrier.init.shared.b64 [%0], %1;" :: "r"(mbar), "r"(count)
                 : "memory");
}
__device__ __forceinline__ void mbar_expect_tx(unsigned mbar, unsigned bytes) {
    asm volatile("mbarrier.arrive.expect_tx.shared.b64 _, [%0], %1;"
                 :: "r"(mbar), "r"(bytes) : "memory");
}
__device__ __forceinline__ void mbar_wait(unsigned mbar, unsigned parity) {
    asm volatile(
        "{\n\t"
        ".reg .pred P1;\n\t"
        "WL_%=:\n\t"
        "mbarrier.try_wait.parity.acquire.cta.shared::cta.b64 P1, [%0], %1, 0x989680;\n\t"
        "@P1 bra.uni WD_%=;\n\t"
        "bra.uni WL_%=;\n\t"
        "WD_%=:\n\t"
        "}"
        :: "r"(mbar), "r"(parity) : "memory");
}
__device__ __forceinline__ void cp_bulk(unsigned dstS, const void* src,
                                        unsigned bytes, unsigned mbarS) {
    asm volatile(
        "cp.async.bulk.shared::cta.global.mbarrier::complete_tx::bytes "
        "[%0], [%1], %2, [%3];"
        :: "r"(dstS), "l"(src), "r"(bytes), "r"(mbarS) : "memory");
}

// per-axis trilinear->original-grid collapse weights (fp32: values are exact
// small rationals; error ~1e-7 is invisible under fp16 quantization)
__device__ __forceinline__ float hvalf(int q, int k, int e, float a) {
    if (q == 0) {
        if (k == 0) return e ? a : (1.0f - a);
        return e ? 1.0f : 0.0f;
    } else {
        if (k == 2) return e ? (1.0f - a) : a;
        return e ? 0.0f : 1.0f;
    }
}

// ---------------- merged setup kernel ----------------------------------------
// grid (64 c, 8 par), block 192 = 6 mt x 32 lanes.
__global__ void setup_all(const float* __restrict__ W,
                          const float* __restrict__ g1, const float* __restrict__ v1,
                          const float* __restrict__ b_def,
                          const float* __restrict__ b1, const float* __restrict__ m1,
                          const float* __restrict__ wcm, const float* __restrict__ bcm,
                          const float* __restrict__ g2, const float* __restrict__ b2,
                          const float* __restrict__ m2, const float* __restrict__ v2) {
    __shared__ float ws[32 * 27];
    int c = blockIdx.x, par = blockIdx.y;
    int tid = threadIdx.x;
    for (int idx = tid; idx < 32 * 27; idx += 192) {
        int co = idx / 27, kk = idx - co * 27;
        ws[idx] = W[co * 1728 + c * 27 + kk];
    }
    __syncthreads();

    int mt = tid >> 5, lane = tid & 31;
    int g = lane >> 2, t4 = lane & 3;
    int qz = (par >> 2) & 1, qy = (par >> 1) & 1, qx = par & 1;

#pragma unroll
    for (int rowbit = 0; rowbit < 2; rowbit++) {
        int m = mt * 16 + g + 8 * rowbit;
        int br = m >> 5, co = m & 31;
        float a = (br == 0) ? 0.0f : (br == 1 ? 0.4f : 0.7f);
        float s1 = g1[co] * rsqrtf(v1[co] + 1e-5f);
        __half hh[2];
#pragma unroll
        for (int h = 0; h < 2; h++) {
            int tap = 2 * t4 + h;
            int ez = (tap >> 2) & 1, ey = (tap >> 1) & 1, ex = tap & 1;
            float hz[3], hy[3], hx[3];
#pragma unroll
            for (int k = 0; k < 3; k++) {
                hz[k] = hvalf(qz, k, ez, a);
                hy[k] = hvalf(qy, k, ey, a);
                hx[k] = hvalf(qx, k, ex, a);
            }
            float sum = 0.f;
#pragma unroll
            for (int kz = 0; kz < 3; kz++)
#pragma unroll
                for (int ky = 0; ky < 3; ky++)
#pragma unroll
                    for (int kx = 0; kx < 3; kx++)
                        sum += ws[co * 27 + kz * 9 + ky * 3 + kx] *
                               (hz[kz] * hy[ky] * hx[kx]);
            hh[h] = __float2half(sum * s1);
        }
        int r = 2 * (c & 1) + rowbit;
        int idx = ((((par * 8 + (c >> 3)) * 4 + ((c >> 1) & 3)) * 6 + mt) * 32 + lane) * 4 + r;
        __half2 hv = __halves2half2(hh[0], hh[1]);
        g_A16[idx] = *(unsigned*)&hv;
    }

    if (blockIdx.x == 0 && blockIdx.y == 0) {
        if (tid < 32) {
            float s1 = g1[tid] * rsqrtf(v1[tid] + 1e-5f);
            g_bias1[tid] = b_def[tid] * s1 + b1[tid] - m1[tid] * s1;
            float s2 = g2[tid] * rsqrtf(v2[tid] + 1e-5f);
            g_bias2[tid] = bcm[tid] * s2 + b2[tid] - m2[tid] * s2;
        }
        for (int idx = tid; idx < 1536; idx += 192) {
            int r = idx & 3, ln = (idx >> 2) & 31, mt2 = (idx >> 7) & 1, k2 = idx >> 8;
            int gg = ln >> 2, tt = ln & 3;
            int m = mt2 * 16 + gg + 8 * (r & 1);
            float s2 = g2[m] * rsqrtf(v2[m] + 1e-5f);
            int ch0 = k2 * 16 + 8 * (r >> 1) + 2 * tt;
            __half2 hv = __halves2half2(__float2half(wcm[m * 96 + ch0] * s2),
                                        __float2half(wcm[m * 96 + ch0 + 1] * s2));
            g_A2[idx] = *(unsigned*)&hv;
        }
    }
}

// ---------------- main fused kernel ------------------------------------------
// block 256 thr = 8 warps; tile = 8(x) x 8(y) x 4(z) orig coords = 256 voxels,
// one parity class. x tile held 32 channels at a time (2 phases) as overlapping
// fp16x2 pairs; A-fragment chunks streamed via cp.async.bulk (TMA) + mbarrier.
#define XT_U32 12960            // 32c * 405 positions (fp16x2 pairs)
#define SA_U32 6144             // 2 x 3072 double-buffered A chunks
#define SA2_U32 1536
#define A_CHUNK_BYTES 12288
#define SMEM_BYTES ((XT_U32 + SA_U32 + SA2_U32 + 96) * 4)

__global__ void __launch_bounds__(256, 2)
conv_main(const float* __restrict__ x, float* __restrict__ out) {
    extern __shared__ unsigned smu[];
    unsigned* xt = smu;                         // also R_t after conv
    unsigned* sA = smu + XT_U32;
    unsigned* sA2 = sA + SA_U32;
    float* b1s = (float*)(sA2 + SA2_U32);
    float* b2s = b1s + 32;
    // mbarriers: 8B-aligned, after biases (u32 idx 20704 -> byte 82816, %8==0)
    unsigned mbar_addr;
    {
        unsigned long long p =
            (unsigned long long)__cvta_generic_to_shared(b2s + 32);
        mbar_addr = (unsigned)p;
    }
    unsigned sA_addr;
    {
        unsigned long long p = (unsigned long long)__cvta_generic_to_shared(sA);
        sA_addr = (unsigned)p;
    }

    const int tid = threadIdx.x;
    const int w = tid >> 5, lane = tid & 31;
    const int g = lane >> 2, t4 = lane & 3;

    const int par = blockIdx.z >> 3;
    const int pzt = blockIdx.z & 7;
    const int qz = (par >> 2) & 1, qy = (par >> 1) & 1, qx = par & 1;
    const int Px0 = blockIdx.x * 8, Py0 = blockIdx.y * 8, Pz0 = pzt * 4;
    const int ox = Px0 - 1 + qx, oy = Py0 - 1 + qy, oz = Pz0 - 1 + qz;

    const unsigned* gA = g_A16 + par * 24576;

    // ---- init mbarriers, then kick off A chunk 0 via TMA bulk ----
    if (tid == 0) {
        mbar_init(mbar_addr, 1);
        mbar_init(mbar_addr + 8, 1);
    }
    __syncthreads();
    if (tid == 0) {
        mbar_expect_tx(mbar_addr, A_CHUNK_BYTES);
        cp_bulk(sA_addr, gA, A_CHUNK_BYTES, mbar_addr);
    }

    // ---- hoisted loader coords: 2 fixed tile positions per thread ----
    const int p0 = tid;                       // 0..255 (<405 always)
    int z0 = p0 / 81, r0 = p0 - z0 * 81, y0 = r0 / 9, x0 = r0 - y0 * 9;
    int gz0 = oz + z0, gy0 = oy + y0, gx0 = ox + x0;
    const bool ok0 = ((unsigned)gz0 < 32u) && ((unsigned)gy0 < 32u) &&
                     ((unsigned)gx0 < 32u);
    const int off0 = (gz0 * 32 + gy0) * 32 + gx0;

    const int p1 = tid + 256;
    const bool has1 = p1 < 405;
    int z1 = p1 / 81, r1 = p1 - z1 * 81, y1 = r1 / 9, x1 = r1 - y1 * 9;
    int gz1 = oz + z1, gy1 = oy + y1, gx1 = ox + x1;
    const bool ok1 = has1 && ((unsigned)gz1 < 32u) && ((unsigned)gy1 < 32u) &&
                     ((unsigned)gx1 < 32u);
    const int off1 = (gz1 * 32 + gy1) * 32 + gx1;

    // x tile as overlapping fp16 pairs: pair idx holds halves (pos, pos+1)
    auto load_half = [&](int phase) {
        const float* xb = x + phase * 32 * 32768;
        __half* hp = (__half*)xt;
#pragma unroll 8
        for (int c = 0; c < 32; c++) {
            float v0 = ok0 ? __ldg(xb + c * 32768 + off0) : 0.f;
            __half h0 = __float2half(v0);
            int i0 = c * 405 + p0;
            hp[2 * i0] = h0;
            if (p0) hp[2 * i0 - 1] = h0;
            if (has1) {
                float v1v = ok1 ? __ldg(xb + c * 32768 + off1) : 0.f;
                __half h1 = __float2half(v1v);
                int i1 = c * 405 + p1;
                hp[2 * i1] = h1;
                hp[2 * i1 - 1] = h1;
            }
        }
    };

    load_half(0);
    for (int i = tid; i < SA2_U32; i += 256) sA2[i] = g_A2[i];
    if (tid < 32) { b1s[tid] = g_bias1[tid]; b2s[tid] = g_bias2[tid]; }

    // ---- per-lane B gather offsets ----
    int boff[4];
#pragma unroll
    for (int nt = 0; nt < 4; nt++) {
        int vox = w * 32 + nt * 8 + g;
        boff[nt] = (vox >> 6) * 81 + ((vox >> 3) & 7) * 9 + (vox & 7);
    }
    const int tapoff = (t4 >> 1) * 81 + (t4 & 1) * 9;

    float d[6][4][4];
#pragma unroll
    for (int i = 0; i < 6; i++)
#pragma unroll
        for (int j = 0; j < 4; j++)
#pragma unroll
            for (int r = 0; r < 4; r++) d[i][j][r] = 0.f;

    // ---- conv GEMM: K = 512 (64 c x 8 taps), 8 chunks of 8 channels ----
#pragma unroll 1
    for (int kc = 0; kc < 8; kc++) {
        // A[kc] ready?  barrier (kc&1), fill index kc>>1, parity (kc>>1)&1
        mbar_wait(mbar_addr + (kc & 1) * 8, (kc >> 1) & 1);
        __syncthreads();   // everyone finished kc-1 (backpressure for refill)
        if (tid == 0 && kc < 7) {
            unsigned mb = mbar_addr + ((kc + 1) & 1) * 8;
            mbar_expect_tx(mb, A_CHUNK_BYTES);
            cp_bulk(sA_addr + ((kc + 1) & 1) * A_CHUNK_BYTES,
                    gA + (kc + 1) * 3072, A_CHUNK_BYTES, mb);
        }
        if (kc == 4) {          // phase boundary: reload x tile with channels 32..63
            load_half(1);
            __syncthreads();
        }
        const unsigned* Ab = sA + (kc & 1) * 3072;
        const int cbase = (kc & 3) * 8;          // local channel base in this half

        unsigned bb[2][2][4];
        {
            const int cw = cbase * 405 + tapoff;
#pragma unroll
            for (int nt = 0; nt < 4; nt++) {
                bb[0][0][nt] = xt[cw + boff[nt]];
                bb[0][1][nt] = xt[cw + boff[nt] + 405];
            }
        }
#pragma unroll
        for (int cpi = 0; cpi < 4; cpi++) {
            const int cur = cpi & 1, nxt = cur ^ 1;
            if (cpi < 3) {
                const int cw = (cbase + 2 * (cpi + 1)) * 405 + tapoff;
#pragma unroll
                for (int nt = 0; nt < 4; nt++) {
                    bb[nxt][0][nt] = xt[cw + boff[nt]];
                    bb[nxt][1][nt] = xt[cw + boff[nt] + 405];
                }
            }
#pragma unroll
            for (int mt = 0; mt < 6; mt++) {
                unsigned a[4];
                *(uint4*)a = *(const uint4*)(Ab + (cpi * 6 + mt) * 128 + lane * 4);
#pragma unroll
                for (int nt = 0; nt < 4; nt++)
                    mma_f16(d[mt][nt], a, bb[cur][0][nt], bb[cur][1][nt]);
            }
        }
    }

    // ---- relu + bias1, stage R_t[vox][96ch] fp16 (stride 100) over xt ----
    __syncthreads();   // all B gathers from xt are done
    {
        __half* Rt = (__half*)xt;
#pragma unroll
        for (int mt = 0; mt < 6; mt++)
#pragma unroll
            for (int nt = 0; nt < 4; nt++)
#pragma unroll
                for (int r = 0; r < 4; r++) {
                    int m = mt * 16 + g + 8 * (r >> 1);
                    int vox = w * 32 + nt * 8 + 2 * t4 + (r & 1);
                    float v = fmaxf(d[mt][nt][r] + b1s[m & 31], 0.f);
                    Rt[vox * 100 + m] = __float2half(v);
                }
    }
    __syncthreads();

    // ---- combine GEMM: D2[32][256] = A2[32][96] * R ----
    float e[2][4][4];
#pragma unroll
    for (int i = 0; i < 2; i++)
#pragma unroll
        for (int j = 0; j < 4; j++)
#pragma unroll
            for (int r = 0; r < 4; r++) e[i][j][r] = 0.f;

#pragma unroll
    for (int k2 = 0; k2 < 6; k2++) {
        unsigned bb0[4], bb1[4];
#pragma unroll
        for (int nt = 0; nt < 4; nt++) {
            int col = w * 32 + nt * 8 + g;
            int base = col * 50 + k2 * 8 + t4;   // u32 index into R_t
            bb0[nt] = xt[base];
            bb1[nt] = xt[base + 4];
        }
#pragma unroll
        for (int mt = 0; mt < 2; mt++) {
            unsigned a[4];
            *(uint4*)a = *(const uint4*)(sA2 + (k2 * 2 + mt) * 128 + lane * 4);
#pragma unroll
            for (int nt = 0; nt < 4; nt++)
                mma_f16(e[mt][nt], a, bb0[nt], bb1[nt]);
        }
    }

    // ---- bias2 + relu + store ----
#pragma unroll
    for (int mt = 0; mt < 2; mt++)
#pragma unroll
        for (int nt = 0; nt < 4; nt++)
#pragma unroll
            for (int r = 0; r < 4; r++) {
                int o = mt * 16 + g + 8 * (r >> 1);
                int vox = w * 32 + nt * 8 + 2 * t4 + (r & 1);
                int vx = vox & 7, vy = (vox >> 3) & 7, vz = vox >> 6;
                int gx = 2 * (Px0 + vx) + qx;
                int gy = 2 * (Py0 + vy) + qy;
                int gz = 2 * (Pz0 + vz) + qz;
                out[o * 262144 + gz * 4096 + gy * 64 + gx] =
                    fmaxf(e[mt][nt][r] + b2s[o], 0.f);
            }
}

// ---------------- launch -----------------------------------------------------
extern "C" void kernel_launch(void* const* d_in, const int* in_sizes, int n_in,
                              void* d_out, int out_size) {
    const float* x      = (const float*)d_in[0];
    const float* w_def  = (const float*)d_in[1];
    const float* b_def  = (const float*)d_in[2];
    const float* bn1_g  = (const float*)d_in[3];
    const float* bn1_b  = (const float*)d_in[4];
    const float* bn1_m  = (const float*)d_in[5];
    const float* bn1_v  = (const float*)d_in[6];
    const float* w_comb = (const float*)d_in[7];
    const float* b_comb = (const float*)d_in[8];
    const float* bn2_g  = (const float*)d_in[9];
    const float* bn2_b  = (const float*)d_in[10];
    const float* bn2_m  = (const float*)d_in[11];
    const float* bn2_v  = (const float*)d_in[12];

    setup_all<<<dim3(64, 8), 192>>>(w_def, bn1_g, bn1_v, b_def, bn1_b, bn1_m,
                                    w_comb, b_comb, bn2_g, bn2_b, bn2_m, bn2_v);

    cudaFuncSetAttribute(conv_main, cudaFuncAttributeMaxDynamicSharedMemorySize,
                         SMEM_BYTES);
    conv_main<<<dim3(4, 4, 64), 256, SMEM_BYTES>>>(x, (float*)d_out);
}